// round 16
// baseline (speedup 1.0000x reference)
#include <cuda_runtime.h>
#include <cuda_bf16.h>
#include <cstdint>

typedef unsigned long long u64;

#define NTHREADS 128
#define SDIM   3
#define LDIM   4
#define IDIM   3
#define TOT    7
#define DT_F   0.01f

#define NCOLS  176     // 64 latent | 96 branch | 7 gate | 3 DT*sdot | 3 yphys | 3 pad
#define KD     16      // K: 10 inputs + bias-one + 5 zeros

// ---- device-global staging (written by pack kernel) ----
__device__ __align__(16) __nv_bfloat16 g_whi[NCOLS * KD];
__device__ __align__(16) __nv_bfloat16 g_wlo[NCOLS * KD];
// g_sw: W2Q (256, DT-scaled) | WB2P (96) | DT*b2 (4 @352) | bb2 (3 @356) | pad
__device__ __align__(16) float g_sw[368];

// ---------- helpers ----------
__device__ __forceinline__ u64 pack2(float lo, float hi) {
    u64 r; asm("mov.b64 %0, {%1, %2};" : "=l"(r) : "f"(lo), "f"(hi)); return r;
}
__device__ __forceinline__ void unpack2(u64 v, float& lo, float& hi) {
    asm("mov.b64 {%0, %1}, %2;" : "=f"(lo), "=f"(hi) : "l"(v));
}
__device__ __forceinline__ u64 ffma2(u64 a, u64 b, u64 c) {
    u64 d; asm("fma.rn.f32x2 %0, %1, %2, %3;" : "=l"(d) : "l"(a), "l"(b), "l"(c));
    return d;
}
__device__ __forceinline__ float fast_tanh(float x) {
    float r; asm("tanh.approx.f32 %0, %1;" : "=f"(r) : "f"(x)); return r;
}
__device__ __forceinline__ float hsum(u64 v) {
    float lo, hi; unpack2(v, lo, hi); return lo + hi;
}

// m16n8k16 row.col bf16 MMA, fp32 accumulate (in-place on d[4])
__device__ __forceinline__ void mma_bf16(float* d,
                                         uint32_t a0, uint32_t a1, uint32_t a2, uint32_t a3,
                                         uint32_t b0, uint32_t b1) {
    asm volatile("mma.sync.aligned.m16n8k16.row.col.f32.bf16.bf16.f32 "
                 "{%0,%1,%2,%3}, {%4,%5,%6,%7}, {%8,%9}, {%0,%1,%2,%3};"
                 : "+f"(d[0]), "+f"(d[1]), "+f"(d[2]), "+f"(d[3])
                 : "r"(a0), "r"(a1), "r"(a2), "r"(a3), "r"(b0), "r"(b1));
}

// ============================================================================
// Pack kernel: build bf16 hi/lo weight matrix [NCOLS x KD] + 2nd-layer tables
// ============================================================================
__global__ void pack_weights(const float* __restrict__ gA,  const float* __restrict__ gBm,
                             const float* __restrict__ gC,  const float* __restrict__ gWz,
                             const float* __restrict__ gbz, const float* __restrict__ gW1,
                             const float* __restrict__ gb1, const float* __restrict__ gW2,
                             const float* __restrict__ gb2, const float* __restrict__ gWb1,
                             const float* __restrict__ gbb1,const float* __restrict__ gWb2,
                             const float* __restrict__ gbb2)
{
    int tid = blockIdx.x * blockDim.x + threadIdx.x;
    int nt = gridDim.x * blockDim.x;
    for (int idx = tid; idx < NCOLS * KD; idx += nt) {
        int n = idx / KD, k = idx % KD;
        float v = 0.0f;
        if (n < 64) {                        // latent layer 1
            if (k < 10) v = gW1[n * 10 + k];
            else if (k == 10) v = gb1[n];
        } else if (n < 160) {                // branch layer 1
            int row = n - 64;
            if (k < 3) v = gWb1[row * 6 + k];
            else if (k >= 7 && k < 10) v = gWb1[row * 6 + 3 + (k - 7)];
            else if (k == 10) v = gbb1[row];
        } else if (n < 167) {                // gate (0.5x folded for sigmoid-via-tanh)
            int i = n - 160;
            if (k < 10) v = 0.5f * gWz[i * 10 + k];
            else if (k == 10) v = 0.5f * gbz[i];
        } else if (n < 170) {                // DT * physics
            int p = n - 167;
            if (k < 3) v = DT_F * gA[p * 3 + k];
            else if (k >= 7 && k < 10) v = DT_F * gBm[p * 3 + (k - 7)];
        } else if (n < 173) {                // y_phys
            int p = n - 170;
            if (k < 3) v = gC[p * 3 + k];
        }
        __nv_bfloat16 hb = __float2bfloat16_rn(v);
        __nv_bfloat16 lb = __float2bfloat16_rn(v - __bfloat162float(hb));
        g_whi[idx] = hb;
        g_wlo[idx] = lb;
    }
    for (int idx = tid; idx < 256; idx += nt) {
        int j = idx >> 2, o = idx & 3;
        g_sw[idx] = DT_F * gW2[o * 64 + j];
    }
    for (int idx = tid; idx < 96; idx += nt) g_sw[256 + idx] = gWb2[idx];
    for (int idx = tid; idx < 4; idx += nt)  g_sw[352 + idx] = DT_F * gb2[idx];
    for (int idx = tid; idx < 3; idx += nt)  g_sw[356 + idx] = gbb2[idx];
    for (int idx = tid; idx < 9; idx += nt)  g_sw[359 + idx] = 0.0f;
}

// ============================================================================
// Fused kernel: HMMA stage-1 (all matrices) + MUFU/scalar epilogue
// Block = 128 thr = 4 warps; each warp owns 32 rows (two m16 tiles).
// ============================================================================
__global__ void __launch_bounds__(NTHREADS, 4)
fused_kernel(const float* __restrict__ state,
             const float* __restrict__ u,
             float* __restrict__ out_state,
             float* __restrict__ out_y)
{
    __shared__ __align__(16) __nv_bfloat16 s_whi[NCOLS * KD];
    __shared__ __align__(16) __nv_bfloat16 s_wlo[NCOLS * KD];
    __shared__ __align__(16) float s_tab[368];
    __shared__ __align__(16) __nv_bfloat16 s_su[4][2][32 * KD];  // [warp][hi/lo]
    __shared__ __align__(16) float s_d[4][32 * 36];              // D chunk, stride 36

    int tid = threadIdx.x;
    // stage weights (uint4 copies)
    {
        const uint4* s1 = (const uint4*)g_whi;
        const uint4* s2 = (const uint4*)g_wlo;
        uint4* d1 = (uint4*)s_whi;
        uint4* d2 = (uint4*)s_wlo;
        for (int i = tid; i < (NCOLS * KD * 2) / 16; i += NTHREADS) {
            d1[i] = s1[i];
            d2[i] = s2[i];
        }
        for (int i = tid; i < 368; i += NTHREADS) s_tab[i] = g_sw[i];
    }
    __syncthreads();

    int warp = tid >> 5, lane = tid & 31;
    size_t row = (size_t)blockIdx.x * 128 + warp * 32 + lane;

    // ---- load su, convert to bf16 hi/lo, stage to smem ----
    float sv[TOT];
    {
        float vals[KD];
        const float* sp = state + row * TOT;
        const float* up = u + row * IDIM;
        #pragma unroll
        for (int i = 0; i < TOT; i++) { sv[i] = __ldg(sp + i); vals[i] = sv[i]; }
        #pragma unroll
        for (int i = 0; i < IDIM; i++) vals[TOT + i] = __ldg(up + i);
        vals[10] = 1.0f;
        #pragma unroll
        for (int i = 11; i < KD; i++) vals[i] = 0.0f;

        uint32_t hi[8], lo[8];
        #pragma unroll
        for (int c = 0; c < 8; c++) {
            float v0 = vals[2 * c], v1 = vals[2 * c + 1];
            __nv_bfloat16 h0 = __float2bfloat16_rn(v0);
            __nv_bfloat16 h1 = __float2bfloat16_rn(v1);
            __nv_bfloat16 g0 = __float2bfloat16_rn(v0 - __bfloat162float(h0));
            __nv_bfloat16 g1 = __float2bfloat16_rn(v1 - __bfloat162float(h1));
            hi[c] = (uint32_t)__bfloat16_as_ushort(h0) |
                    ((uint32_t)__bfloat16_as_ushort(h1) << 16);
            lo[c] = (uint32_t)__bfloat16_as_ushort(g0) |
                    ((uint32_t)__bfloat16_as_ushort(g1) << 16);
        }
        uint4* dh = (uint4*)(s_su[warp][0] + lane * KD);
        uint4* dl = (uint4*)(s_su[warp][1] + lane * KD);
        dh[0] = make_uint4(hi[0], hi[1], hi[2], hi[3]);
        dh[1] = make_uint4(hi[4], hi[5], hi[6], hi[7]);
        dl[0] = make_uint4(lo[0], lo[1], lo[2], lo[3]);
        dl[1] = make_uint4(lo[4], lo[5], lo[6], lo[7]);
    }
    __syncwarp();

    // ---- build A fragments: afr[mtile][split][4] ----
    int g = lane >> 2;
    int c = (lane & 3) * 2;       // bf16 col index (even)
    uint32_t afr[2][2][4];
    #pragma unroll
    for (int mt = 0; mt < 2; mt++) {
        #pragma unroll
        for (int sp2 = 0; sp2 < 2; sp2++) {
            const __nv_bfloat16* base = s_su[warp][sp2] + (mt * 16 + g) * KD;
            afr[mt][sp2][0] = *(const uint32_t*)(base + c);
            afr[mt][sp2][1] = *(const uint32_t*)(base + 8 * KD + c);
            afr[mt][sp2][2] = *(const uint32_t*)(base + c + 8);
            afr[mt][sp2][3] = *(const uint32_t*)(base + 8 * KD + c + 8);
        }
    }

    // accumulators
    u64 acc01 = *(const u64*)(s_tab + 352);   // (DT*b2_0, DT*b2_1)
    u64 acc23 = *(const u64*)(s_tab + 354);
    float resf[SDIM];
    float* dwarp = s_d[warp];

    #pragma unroll
    for (int ct = 0; ct < 6; ct++) {
        const int ntl = (ct < 5) ? 4 : 2;
        float d[4][2][4];
        #pragma unroll
        for (int nt = 0; nt < 4; nt++)
            #pragma unroll
            for (int mt = 0; mt < 2; mt++)
                #pragma unroll
                for (int q = 0; q < 4; q++) d[nt][mt][q] = 0.0f;

        #pragma unroll
        for (int nt = 0; nt < 4; nt++) {
            if (nt >= ntl) break;
            int n = ct * 32 + nt * 8 + g;
            uint32_t bh0 = *(const uint32_t*)(s_whi + n * KD + c);
            uint32_t bh1 = *(const uint32_t*)(s_whi + n * KD + c + 8);
            uint32_t bl0 = *(const uint32_t*)(s_wlo + n * KD + c);
            uint32_t bl1 = *(const uint32_t*)(s_wlo + n * KD + c + 8);
            #pragma unroll
            for (int mt = 0; mt < 2; mt++) {
                mma_bf16(d[nt][mt], afr[mt][0][0], afr[mt][0][1], afr[mt][0][2], afr[mt][0][3], bh0, bh1);
                mma_bf16(d[nt][mt], afr[mt][1][0], afr[mt][1][1], afr[mt][1][2], afr[mt][1][3], bh0, bh1);
                mma_bf16(d[nt][mt], afr[mt][0][0], afr[mt][0][1], afr[mt][0][2], afr[mt][0][3], bl0, bl1);
            }
        }
        // store D fragments to per-warp smem (stride 36 floats)
        #pragma unroll
        for (int nt = 0; nt < 4; nt++) {
            if (nt >= ntl) break;
            int colb = nt * 8 + (lane & 3) * 2;
            #pragma unroll
            for (int mt = 0; mt < 2; mt++) {
                *(float2*)(dwarp + (mt * 16 + g) * 36 + colb) =
                    make_float2(d[nt][mt][0], d[nt][mt][1]);
                *(float2*)(dwarp + (mt * 16 + g + 8) * 36 + colb) =
                    make_float2(d[nt][mt][2], d[nt][mt][3]);
            }
        }
        __syncwarp();

        // ---- per-row epilogue for this chunk (thread row = lane) ----
        const float* drow = dwarp + lane * 36;
        if (ct < 2) {
            // latent cols: tanh -> W2 accumulation
            #pragma unroll
            for (int i = 0; i < 32; i++) {
                float h = fast_tanh(drow[i]);
                u64 hh = pack2(h, h);
                const ulonglong2 ww = *(const ulonglong2*)(s_tab + (ct * 32 + i) * 4);
                acc01 = ffma2(ww.x, hh, acc01);
                acc23 = ffma2(ww.y, hh, acc23);
            }
        } else if (ct < 5) {
            // branch cols: tanh -> Wb2 dot
            int k = ct - 2;
            u64 r = 0ull;
            #pragma unroll
            for (int i = 0; i < 32; i += 2) {
                u64 wp = *(const u64*)(s_tab + 256 + k * 32 + i);
                r = ffma2(wp, pack2(fast_tanh(drow[i]), fast_tanh(drow[i + 1])), r);
            }
            resf[k] = hsum(r);
        } else {
            // final 16 cols: gate(0..6), DT*sdot(7..9), yphys(10..12)
            float tv[16];
            #pragma unroll
            for (int i = 0; i < 16; i += 4) {
                float4 v4 = *(const float4*)(drow + i);
                tv[i] = v4.x; tv[i + 1] = v4.y; tv[i + 2] = v4.z; tv[i + 3] = v4.w;
            }
            float* os = out_state + row * TOT;
            #pragma unroll
            for (int i = 0; i < SDIM; i++) {
                float z = fmaf(0.5f, fast_tanh(tv[i]), 0.5f);
                os[i] = fmaf(z, tv[7 + i], sv[i]);
            }
            float l0, l1, l2, l3;
            unpack2(acc01, l0, l1);
            unpack2(acc23, l2, l3);
            float ld[LDIM] = {l0, l1, l2, l3};
            #pragma unroll
            for (int o = 0; o < LDIM; o++) {
                float z = fmaf(0.5f, fast_tanh(tv[3 + o]), 0.5f);
                os[SDIM + o] = fmaf(z, ld[o], sv[SDIM + o]);
            }
            float* oy = out_y + row * SDIM;
            #pragma unroll
            for (int k = 0; k < SDIM; k++)
                oy[k] = tv[10 + k] + resf[k] + s_tab[356 + k];
        }
        __syncwarp();
    }
}

extern "C" void kernel_launch(void* const* d_in, const int* in_sizes, int n_in,
                              void* d_out, int out_size) {
    const float* state = (const float*)d_in[0];
    const float* u     = (const float*)d_in[1];
    const float* A     = (const float*)d_in[2];
    const float* Bm    = (const float*)d_in[3];
    const float* C     = (const float*)d_in[4];
    const float* Wz    = (const float*)d_in[5];
    const float* bz    = (const float*)d_in[6];
    const float* W1    = (const float*)d_in[7];
    const float* b1    = (const float*)d_in[8];
    const float* W2    = (const float*)d_in[9];
    const float* b2    = (const float*)d_in[10];
    const float* Wb1   = (const float*)d_in[11];
    const float* bb1   = (const float*)d_in[12];
    const float* Wb2   = (const float*)d_in[13];
    const float* bb2   = (const float*)d_in[14];

    int B = in_sizes[0] / TOT;
    float* out       = (float*)d_out;
    float* out_state = out;                      // [B, 7]
    float* out_y     = out + (size_t)B * TOT;    // [B, 3]

    pack_weights<<<16, 128>>>(A, Bm, C, Wz, bz, W1, b1, W2, b2,
                              Wb1, bb1, Wb2, bb2);

    int grid = B / 128;                          // B = 2^21 -> 16384 blocks
    fused_kernel<<<grid, NTHREADS>>>(state, u, out_state, out_y);
}

// round 17
// speedup vs baseline: 1.5057x; 1.5057x over previous
#include <cuda_runtime.h>
#include <cuda_bf16.h>
#include <cstdint>

typedef unsigned long long u64;

#define NTHREADS 128
#define SDIM   3
#define LDIM   4
#define IDIM   3
#define TOT    7
#define DT_F   0.01f

#define NCOLS  176     // 64 latent | 96 branch | 7 gate | 3 DT*sdot | 3 yphys | 3 pad
#define KD     16      // K: 10 inputs + bias-one + 5 zeros
#define FSTR   45      // final bounce-buffer stride (odd -> conflict-free)

// ---- device-global staging (written by pack kernel) ----
__device__ __align__(16) __nv_bfloat16 g_whi[NCOLS * KD];
__device__ __align__(16) __nv_bfloat16 g_wlo[NCOLS * KD];
// g_sw: W2Q (256, DT-scaled) | WB2P (96) | DT*b2 (4 @352) | bb2 (3 @356) | pad
__device__ __align__(16) float g_sw[368];

// ---------- helpers ----------
__device__ __forceinline__ u64 pack2(float lo, float hi) {
    u64 r; asm("mov.b64 %0, {%1, %2};" : "=l"(r) : "f"(lo), "f"(hi)); return r;
}
__device__ __forceinline__ void unpack2(u64 v, float& lo, float& hi) {
    asm("mov.b64 {%0, %1}, %2;" : "=f"(lo), "=f"(hi) : "l"(v));
}
__device__ __forceinline__ u64 ffma2(u64 a, u64 b, u64 c) {
    u64 d; asm("fma.rn.f32x2 %0, %1, %2, %3;" : "=l"(d) : "l"(a), "l"(b), "l"(c));
    return d;
}
__device__ __forceinline__ float fast_tanh(float x) {
    float r; asm("tanh.approx.f32 %0, %1;" : "=f"(r) : "f"(x)); return r;
}
__device__ __forceinline__ float hsum(u64 v) {
    float lo, hi; unpack2(v, lo, hi); return lo + hi;
}
__device__ __forceinline__ float getlo(u64 v) {
    float lo, hi; unpack2(v, lo, hi); return lo;
}
__device__ __forceinline__ float gethi(u64 v) {
    float lo, hi; unpack2(v, lo, hi); return hi;
}

// m16n8k16 row.col bf16 MMA, fp32 accumulate (in-place on d[4])
__device__ __forceinline__ void mma_bf16(float* d,
                                         const uint32_t* a,
                                         uint32_t b0, uint32_t b1) {
    asm volatile("mma.sync.aligned.m16n8k16.row.col.f32.bf16.bf16.f32 "
                 "{%0,%1,%2,%3}, {%4,%5,%6,%7}, {%8,%9}, {%0,%1,%2,%3};"
                 : "+f"(d[0]), "+f"(d[1]), "+f"(d[2]), "+f"(d[3])
                 : "r"(a[0]), "r"(a[1]), "r"(a[2]), "r"(a[3]), "r"(b0), "r"(b1));
}

// ============================================================================
// Pack kernel
// ============================================================================
__global__ void pack_weights(const float* __restrict__ gA,  const float* __restrict__ gBm,
                             const float* __restrict__ gC,  const float* __restrict__ gWz,
                             const float* __restrict__ gbz, const float* __restrict__ gW1,
                             const float* __restrict__ gb1, const float* __restrict__ gW2,
                             const float* __restrict__ gb2, const float* __restrict__ gWb1,
                             const float* __restrict__ gbb1,const float* __restrict__ gWb2,
                             const float* __restrict__ gbb2)
{
    int tid = blockIdx.x * blockDim.x + threadIdx.x;
    int nt = gridDim.x * blockDim.x;
    for (int idx = tid; idx < NCOLS * KD; idx += nt) {
        int n = idx / KD, k = idx % KD;
        float v = 0.0f;
        if (n < 64) {
            if (k < 10) v = gW1[n * 10 + k];
            else if (k == 10) v = gb1[n];
        } else if (n < 160) {
            int row = n - 64;
            if (k < 3) v = gWb1[row * 6 + k];
            else if (k >= 7 && k < 10) v = gWb1[row * 6 + 3 + (k - 7)];
            else if (k == 10) v = gbb1[row];
        } else if (n < 167) {
            int i = n - 160;
            if (k < 10) v = 0.5f * gWz[i * 10 + k];
            else if (k == 10) v = 0.5f * gbz[i];
        } else if (n < 170) {
            int p = n - 167;
            if (k < 3) v = DT_F * gA[p * 3 + k];
            else if (k >= 7 && k < 10) v = DT_F * gBm[p * 3 + (k - 7)];
        } else if (n < 173) {
            int p = n - 170;
            if (k < 3) v = gC[p * 3 + k];
        }
        __nv_bfloat16 hb = __float2bfloat16_rn(v);
        __nv_bfloat16 lb = __float2bfloat16_rn(v - __bfloat162float(hb));
        g_whi[idx] = hb;
        g_wlo[idx] = lb;
    }
    for (int idx = tid; idx < 256; idx += nt) {
        int j = idx >> 2, o = idx & 3;
        g_sw[idx] = DT_F * gW2[o * 64 + j];
    }
    for (int idx = tid; idx < 96; idx += nt) g_sw[256 + idx] = gWb2[idx];
    for (int idx = tid; idx < 4; idx += nt)  g_sw[352 + idx] = DT_F * gb2[idx];
    for (int idx = tid; idx < 3; idx += nt)  g_sw[356 + idx] = gbb2[idx];
    for (int idx = tid; idx < 9; idx += nt)  g_sw[359 + idx] = 0.0f;
}

// ============================================================================
// Fused kernel: HMMA stage-1 + in-register fragment epilogue
// Block = 128 thr = 4 warps; warp owns 32 rows; thread(g,q) owns row slots
// {g, g+8, g+16, g+24} and cols {nt*8+2q, nt*8+2q+1} per n-tile.
// ============================================================================
__global__ void __launch_bounds__(NTHREADS, 4)
fused_kernel(const float* __restrict__ state,
             const float* __restrict__ u,
             float* __restrict__ out_state,
             float* __restrict__ out_y)
{
    __shared__ __align__(16) __nv_bfloat16 s_whi[NCOLS * KD];
    __shared__ __align__(16) __nv_bfloat16 s_wlo[NCOLS * KD];
    __shared__ __align__(16) float s_tab[368];
    __shared__ __align__(16) __nv_bfloat16 s_su[4][2][32 * KD];
    __shared__ __align__(16) float s_fin[4][32 * FSTR];

    int tid = threadIdx.x;
    {
        const uint4* s1 = (const uint4*)g_whi;
        const uint4* s2 = (const uint4*)g_wlo;
        uint4* d1 = (uint4*)s_whi;
        uint4* d2 = (uint4*)s_wlo;
        for (int i = tid; i < (NCOLS * KD * 2) / 16; i += NTHREADS) {
            d1[i] = s1[i];
            d2[i] = s2[i];
        }
        for (int i = tid; i < 368; i += NTHREADS) s_tab[i] = g_sw[i];
    }
    __syncthreads();

    int warp = tid >> 5, lane = tid & 31;
    int g = lane >> 2, q = lane & 3;
    int cq = q * 2;
    size_t row = (size_t)blockIdx.x * 128 + warp * 32 + lane;

    // ---- load su, bf16 hi/lo, stage to smem ----
    float sv[TOT];
    {
        float vals[KD];
        const float* sp = state + row * TOT;
        const float* up = u + row * IDIM;
        #pragma unroll
        for (int i = 0; i < TOT; i++) { sv[i] = __ldg(sp + i); vals[i] = sv[i]; }
        #pragma unroll
        for (int i = 0; i < IDIM; i++) vals[TOT + i] = __ldg(up + i);
        vals[10] = 1.0f;
        #pragma unroll
        for (int i = 11; i < KD; i++) vals[i] = 0.0f;

        uint32_t hi[8], lo[8];
        #pragma unroll
        for (int c2 = 0; c2 < 8; c2++) {
            float v0 = vals[2 * c2], v1 = vals[2 * c2 + 1];
            __nv_bfloat16 h0 = __float2bfloat16_rn(v0);
            __nv_bfloat16 h1 = __float2bfloat16_rn(v1);
            __nv_bfloat16 e0 = __float2bfloat16_rn(v0 - __bfloat162float(h0));
            __nv_bfloat16 e1 = __float2bfloat16_rn(v1 - __bfloat162float(h1));
            hi[c2] = (uint32_t)__bfloat16_as_ushort(h0) |
                     ((uint32_t)__bfloat16_as_ushort(h1) << 16);
            lo[c2] = (uint32_t)__bfloat16_as_ushort(e0) |
                     ((uint32_t)__bfloat16_as_ushort(e1) << 16);
        }
        uint4* dh = (uint4*)(s_su[warp][0] + lane * KD);
        uint4* dl = (uint4*)(s_su[warp][1] + lane * KD);
        dh[0] = make_uint4(hi[0], hi[1], hi[2], hi[3]);
        dh[1] = make_uint4(hi[4], hi[5], hi[6], hi[7]);
        dl[0] = make_uint4(lo[0], lo[1], lo[2], lo[3]);
        dl[1] = make_uint4(lo[4], lo[5], lo[6], lo[7]);
    }
    __syncwarp();

    // ---- A fragments: afr[mtile][split][4] ----
    uint32_t afr[2][2][4];
    #pragma unroll
    for (int mt = 0; mt < 2; mt++) {
        #pragma unroll
        for (int sp2 = 0; sp2 < 2; sp2++) {
            const __nv_bfloat16* base = s_su[warp][sp2] + (mt * 16 + g) * KD;
            afr[mt][sp2][0] = *(const uint32_t*)(base + cq);
            afr[mt][sp2][1] = *(const uint32_t*)(base + 8 * KD + cq);
            afr[mt][sp2][2] = *(const uint32_t*)(base + cq + 8);
            afr[mt][sp2][3] = *(const uint32_t*)(base + 8 * KD + cq + 8);
        }
    }

    // partial accumulators per row slot s (rows g+8s)
    u64 accA[4], accB[4];          // (dot0,dot1), (dot2,dot3) per slot
    #pragma unroll
    for (int s = 0; s < 4; s++) { accA[s] = 0ull; accB[s] = 0ull; }
    float resfv[3][4];
    u64 respk[4];
    float* fw = s_fin[warp];

    #pragma unroll
    for (int nt = 0; nt < 22; nt++) {
        int n = nt * 8 + g;
        uint32_t bh0 = *(const uint32_t*)(s_whi + n * KD + cq);
        uint32_t bh1 = *(const uint32_t*)(s_whi + n * KD + cq + 8);
        uint32_t bl0 = *(const uint32_t*)(s_wlo + n * KD + cq);
        uint32_t bl1 = *(const uint32_t*)(s_wlo + n * KD + cq + 8);
        float d0[4] = {0, 0, 0, 0}, d1[4] = {0, 0, 0, 0};
        mma_bf16(d0, afr[0][0], bh0, bh1);
        mma_bf16(d0, afr[0][1], bh0, bh1);
        mma_bf16(d0, afr[0][0], bl0, bl1);
        mma_bf16(d1, afr[1][0], bh0, bh1);
        mma_bf16(d1, afr[1][1], bh0, bh1);
        mma_bf16(d1, afr[1][0], bl0, bl1);
        // slot s values: s0=(d0[0],d0[1]) s1=(d0[2],d0[3]) s2=(d1[0],d1[1]) s3=(d1[2],d1[3])
        if (nt < 8) {
            // latent: tanh -> W2 partial acc (cols j0=nt*8+cq, j1=j0+1)
            int j0 = nt * 8 + cq;
            ulonglong2 w0 = *(const ulonglong2*)(s_tab + j0 * 4);
            ulonglong2 w1 = *(const ulonglong2*)(s_tab + (j0 + 1) * 4);
            float hv[8];
            hv[0] = fast_tanh(d0[0]); hv[1] = fast_tanh(d0[1]);
            hv[2] = fast_tanh(d0[2]); hv[3] = fast_tanh(d0[3]);
            hv[4] = fast_tanh(d1[0]); hv[5] = fast_tanh(d1[1]);
            hv[6] = fast_tanh(d1[2]); hv[7] = fast_tanh(d1[3]);
            #pragma unroll
            for (int s = 0; s < 4; s++) {
                u64 h0 = pack2(hv[s * 2], hv[s * 2]);
                u64 h1 = pack2(hv[s * 2 + 1], hv[s * 2 + 1]);
                accA[s] = ffma2(w0.x, h0, accA[s]);
                accB[s] = ffma2(w0.y, h0, accB[s]);
                accA[s] = ffma2(w1.x, h1, accA[s]);
                accB[s] = ffma2(w1.y, h1, accB[s]);
            }
        } else if (nt < 20) {
            // branch: tanh -> Wb2 partial dot
            int bi = nt - 8;
            int kb = bi >> 2;
            int ii = (bi & 3) * 8 + cq;
            if ((bi & 3) == 0) {
                respk[0] = 0ull; respk[1] = 0ull; respk[2] = 0ull; respk[3] = 0ull;
            }
            u64 wp = *(const u64*)(s_tab + 256 + kb * 32 + ii);
            respk[0] = ffma2(wp, pack2(fast_tanh(d0[0]), fast_tanh(d0[1])), respk[0]);
            respk[1] = ffma2(wp, pack2(fast_tanh(d0[2]), fast_tanh(d0[3])), respk[1]);
            respk[2] = ffma2(wp, pack2(fast_tanh(d1[0]), fast_tanh(d1[1])), respk[2]);
            respk[3] = ffma2(wp, pack2(fast_tanh(d1[2]), fast_tanh(d1[3])), respk[3]);
            if ((bi & 3) == 3) {
                #pragma unroll
                for (int s = 0; s < 4; s++) resfv[kb][s] = hsum(respk[s]);
            }
        } else {
            // final 16 cols: scatter raw D to bounce buffer (stride FSTR, scalar)
            int colb = (nt - 20) * 8 + cq;
            fw[g * FSTR + colb] = d0[0];
            fw[g * FSTR + colb + 1] = d0[1];
            fw[(g + 8) * FSTR + colb] = d0[2];
            fw[(g + 8) * FSTR + colb + 1] = d0[3];
            fw[(g + 16) * FSTR + colb] = d1[0];
            fw[(g + 16) * FSTR + colb + 1] = d1[1];
            fw[(g + 24) * FSTR + colb] = d1[2];
            fw[(g + 24) * FSTR + colb + 1] = d1[3];
        }
    }

    // latent bias: add DT*b2 once per row (fold into slot partials for q==0 only)
    if (q == 0) {
        u64 bA = *(const u64*)(s_tab + 352);
        u64 bB = *(const u64*)(s_tab + 354);
        #pragma unroll
        for (int s = 0; s < 4; s++) {
            float a0, a1, b0, b1, c0, c1, e0, e1;
            unpack2(accA[s], a0, a1); unpack2(bA, c0, c1);
            unpack2(accB[s], b0, b1); unpack2(bB, e0, e1);
            accA[s] = pack2(a0 + c0, a1 + c1);
            accB[s] = pack2(b0 + e0, b1 + e1);
        }
    }

    // store per-slot partials: row g+8s, cols 16 + q*7 + [0..6]
    #pragma unroll
    for (int s = 0; s < 4; s++) {
        float* pb = fw + (g + 8 * s) * FSTR + 16 + q * 7;
        pb[0] = getlo(accA[s]);
        pb[1] = gethi(accA[s]);
        pb[2] = getlo(accB[s]);
        pb[3] = gethi(accB[s]);
        pb[4] = resfv[0][s];
        pb[5] = resfv[1][s];
        pb[6] = resfv[2][s];
    }
    __syncwarp();

    // ---- final per-row epilogue (thread row = lane) ----
    {
        const float* fr = fw + lane * FSTR;
        float tv[16];
        #pragma unroll
        for (int i = 0; i < 16; i++) tv[i] = fr[i];
        float accf[4], rf[3];
        #pragma unroll
        for (int o = 0; o < 4; o++)
            accf[o] = fr[16 + o] + fr[23 + o] + fr[30 + o] + fr[37 + o];
        #pragma unroll
        for (int k = 0; k < 3; k++)
            rf[k] = fr[20 + k] + fr[27 + k] + fr[34 + k] + fr[41 + k];

        float* os = out_state + row * TOT;
        #pragma unroll
        for (int i = 0; i < SDIM; i++) {
            float z = fmaf(0.5f, fast_tanh(tv[i]), 0.5f);
            os[i] = fmaf(z, tv[7 + i], sv[i]);
        }
        #pragma unroll
        for (int o = 0; o < LDIM; o++) {
            float z = fmaf(0.5f, fast_tanh(tv[3 + o]), 0.5f);
            os[SDIM + o] = fmaf(z, accf[o], sv[SDIM + o]);
        }
        float* oy = out_y + row * SDIM;
        #pragma unroll
        for (int k = 0; k < SDIM; k++)
            oy[k] = tv[10 + k] + rf[k] + s_tab[356 + k];
    }
}

extern "C" void kernel_launch(void* const* d_in, const int* in_sizes, int n_in,
                              void* d_out, int out_size) {
    const float* state = (const float*)d_in[0];
    const float* u     = (const float*)d_in[1];
    const float* A     = (const float*)d_in[2];
    const float* Bm    = (const float*)d_in[3];
    const float* C     = (const float*)d_in[4];
    const float* Wz    = (const float*)d_in[5];
    const float* bz    = (const float*)d_in[6];
    const float* W1    = (const float*)d_in[7];
    const float* b1    = (const float*)d_in[8];
    const float* W2    = (const float*)d_in[9];
    const float* b2    = (const float*)d_in[10];
    const float* Wb1   = (const float*)d_in[11];
    const float* bb1   = (const float*)d_in[12];
    const float* Wb2   = (const float*)d_in[13];
    const float* bb2   = (const float*)d_in[14];

    int B = in_sizes[0] / TOT;
    float* out       = (float*)d_out;
    float* out_state = out;                      // [B, 7]
    float* out_y     = out + (size_t)B * TOT;    // [B, 3]

    pack_weights<<<16, 128>>>(A, Bm, C, Wz, bz, W1, b1, W2, b2,
                              Wb1, bb1, Wb2, bb2);

    int grid = B / 128;                          // 16384 blocks
    fused_kernel<<<grid, NTHREADS>>>(state, u, out_state, out_y);
}